// round 3
// baseline (speedup 1.0000x reference)
#include <cuda_runtime.h>
#include <cuda_fp16.h>
#include <math.h>

#define S_LEN 8192
#define TAGS 2048
#define RPB 14
#define NB 147                 // 146*14 + 4 = 2048 rows
#define TPB 512
#define NWARP 16
#define JW (TAGS / NWARP)      // 128 j-columns per warp
#define JL (JW / 2)            // 64 j per lane
#define EH2 (JL / 2)           // 32 half2 E registers per lane
#define PSTRIDE 20             // partial row stride (floats): 16B-aligned, low-conflict
#define ALPHA 8.0f
#define START_IDX 0
#define END_IDX 1

// Persistent device state (no allocations allowed).
__device__ float g_Mbuf[S_LEN + 2];   // Mbuf[t] = max of r_t (Mbuf[0] = 1); nonneg => u32 red.max OK
__device__ float g_wbuf[2][TAGS];     // double-buffered carried vector
__device__ unsigned g_arrive;         // monotonic arrive counter

__global__ void crf_init() {
    int i = blockIdx.x * blockDim.x + threadIdx.x;
    int n = gridDim.x * blockDim.x;
    for (int t = i; t < S_LEN + 2; t += n) g_Mbuf[t] = (t == 0) ? 1.0f : 0.0f;
    for (int j = i; j < TAGS; j += n) {
        g_wbuf[0][j] = (j == START_IDX) ? 1.0f : 0.0f;
        g_wbuf[1][j] = 0.0f;
    }
    if (i == 0) g_arrive = 0u;
}

__device__ __forceinline__ __half2 f_as_h2(const float& f) {
    return *reinterpret_cast<const __half2*>(&f);
}
__device__ __forceinline__ float4 add4(float4 a, float4 b) {
    return make_float4(a.x + b.x, a.y + b.y, a.z + b.z, a.w + b.w);
}

__global__ void __launch_bounds__(TPB, 1) crf_main(const float* __restrict__ h,
                                                   const float* __restrict__ tr,
                                                   float* __restrict__ out) {
    __shared__ __half2 vbuf[TAGS / 2];          // 4KB: current v as half2 (warp-private slices)
    __shared__ float P[2 * RPB][PSTRIDE];       // transposed partials: P[laneSlot][warp]
    __shared__ double redd[TPB];                // epilogue scratch

    const int tid = threadIdx.x;
    const int warp = tid >> 5, lane = tid & 31;
    const int b = blockIdx.x;
    const int row0 = b * RPB;
    int nrows = TAGS - row0; if (nrows > RPB) nrows = RPB;

    const bool act = lane < 2 * RPB;
    const int row = (lane < RPB) ? lane : lane - RPB;
    const int jh = (lane >= RPB) ? 1 : 0;

    // ---- One-time: this lane's E chunk = exp(transitions) -> 32 half2 registers ----
    __half2 E2[EH2];
    if (act && row < nrows) {
        const float* trow = tr + (size_t)(row0 + row) * TAGS + warp * JW + jh * JL;
#pragma unroll
        for (int q = 0; q < EH2; q++)
            E2[q] = __floats2half2_rn(__expf(trow[2 * q]), __expf(trow[2 * q + 1]));
    } else {
#pragma unroll
        for (int q = 0; q < EH2; q++) E2[q] = __floats2half2_rn(0.f, 0.f);
    }

    const float4* v4base = reinterpret_cast<const float4*>(vbuf) + (warp * 16 + jh * 8);
    const bool comb = (warp == 0) && (lane < nrows);

    // h pipeline: hv holds emissions for the step about to run (loaded one step ahead).
    float hv = comb ? __ldcg(h + row0 + lane) : 0.f;

    for (int t = 0; t < S_LEN; t++) {
        // ---- wait for step-t inputs (one poller, block release) ----
        if (t > 0) {
            if (tid == 0) {
                unsigned target = (unsigned)t * NB, c;
                do {
                    asm volatile("ld.relaxed.gpu.global.u32 %0, [%1];"
                                 : "=r"(c) : "l"(&g_arrive));
                } while (c < target);
                asm volatile("fence.acq_rel.gpu;" ::: "memory");
            }
            __syncthreads();
        }

        // ---- off-critical-path: exp of current emissions, prefetch next step's ----
        float ehv = __expf(hv);
        if (comb && t + 1 < S_LEN)
            hv = __ldcg(h + (size_t)(t + 1) * TAGS + row0 + lane);

        // ---- v prep: scale + fp16 convert into warp-private smem slice ----
        {
            float m = __ldcg(&g_Mbuf[t]);
            float s = __fdividef(ALPHA, m);
            float4 x = __ldcg(reinterpret_cast<const float4*>(g_wbuf[t & 1]) + tid);
            vbuf[2 * tid]     = __floats2half2_rn(x.x * s, x.y * s);
            vbuf[2 * tid + 1] = __floats2half2_rn(x.z * s, x.w * s);
        }
        __syncwarp();   // vbuf slice is produced and consumed by this warp only

        // ---- 64-j dot fragment per lane: 4 chains of 8 half2 (16 fp16 terms) ----
        float f0 = 0.f, f1 = 0.f;
#pragma unroll
        for (int c = 0; c < 4; c++) {
            float4 va = v4base[2 * c];
            float4 vb = v4base[2 * c + 1];
            __half2 acc = __hmul2(E2[8 * c + 0], f_as_h2(va.x));
            acc = __hfma2(E2[8 * c + 1], f_as_h2(va.y), acc);
            acc = __hfma2(E2[8 * c + 2], f_as_h2(va.z), acc);
            acc = __hfma2(E2[8 * c + 3], f_as_h2(va.w), acc);
            acc = __hfma2(E2[8 * c + 4], f_as_h2(vb.x), acc);
            acc = __hfma2(E2[8 * c + 5], f_as_h2(vb.y), acc);
            acc = __hfma2(E2[8 * c + 6], f_as_h2(vb.z), acc);
            acc = __hfma2(E2[8 * c + 7], f_as_h2(vb.w), acc);
            float2 ff = __half22float2(acc);
            f0 += ff.x; f1 += ff.y;
        }
        if (act) P[lane][warp] = f0 + f1;
        __syncthreads();

        // ---- combine (warp 0), publish w + max, arrive ----
        if (warp == 0) {
            if (comb) {
                const float4* Pr = reinterpret_cast<const float4*>(P[lane]);
                const float4* Qr = reinterpret_cast<const float4*>(P[lane + RPB]);
                float4 s4 = add4(add4(add4(Pr[0], Pr[1]), add4(Pr[2], Pr[3])),
                                 add4(add4(Qr[0], Qr[1]), add4(Qr[2], Qr[3])));
                float sum = (s4.x + s4.y) + (s4.z + s4.w);
                float wv = ehv * sum;
                __stcg(&g_wbuf[(t + 1) & 1][row0 + lane], wv);
                asm volatile("red.relaxed.gpu.global.max.u32 [%0], %1;"
                             :: "l"(reinterpret_cast<unsigned*>(&g_Mbuf[t + 1])),
                                "r"(__float_as_uint(wv)) : "memory");
            }
            __syncwarp();
            if (lane == 0) {
                asm volatile("fence.acq_rel.gpu;" ::: "memory");
                asm volatile("red.relaxed.gpu.global.add.u32 [%0], %1;"
                             :: "l"(&g_arrive), "r"(1u) : "memory");
            }
        }
        // (top-of-loop syncthreads gates reuse of vbuf/P)
    }

    // ---- epilogue: block 0 only ----
    if (b == 0) {
        if (tid == 0) {
            unsigned target = (unsigned)NB * (unsigned)S_LEN, c;
            do {
                asm volatile("ld.relaxed.gpu.global.u32 %0, [%1];" : "=r"(c) : "l"(&g_arrive));
            } while (c < target);
            asm volatile("fence.acq_rel.gpu;" ::: "memory");
        }
        __syncthreads();

        float* redf = reinterpret_cast<float*>(vbuf);   // 512 floats <= 4KB
        const float* rS = g_wbuf[S_LEN & 1];
        float dpart = 0.f;
        for (int j = tid; j < TAGS; j += TPB)
            dpart += __ldcg(&rS[j]) * __expf(tr[(size_t)END_IDX * TAGS + j]);
        double lpart = 0.0;
        for (int t = tid; t < S_LEN; t += TPB)
            lpart += log((double)__ldcg(&g_Mbuf[t]));
        redf[tid] = dpart;
        redd[tid] = lpart;
        __syncthreads();
        for (int off = TPB / 2; off > 0; off >>= 1) {
            if (tid < off) { redf[tid] += redf[tid + off]; redd[tid] += redd[tid + off]; }
            __syncthreads();
        }
        if (tid == 0)
            out[0] = (float)(redd[0] + log((double)redf[0]) -
                             (double)S_LEN * log((double)ALPHA));
    }
}

extern "C" void kernel_launch(void* const* d_in, const int* in_sizes, int n_in,
                              void* d_out, int out_size) {
    const float* a = (const float*)d_in[0];
    const float* bb = (const float*)d_in[1];
    const float* h;
    const float* tr;
    if (in_sizes[0] == S_LEN * TAGS) { h = a; tr = bb; }
    else { h = bb; tr = a; }

    crf_init<<<64, 256>>>();
    crf_main<<<NB, TPB>>>(h, tr, (float*)d_out);
}

// round 5
// speedup vs baseline: 1.2764x; 1.2764x over previous
#include <cuda_runtime.h>
#include <cuda_fp16.h>
#include <math.h>

#define S_LEN 8192
#define TAGS 2048
#define RPB 14
#define NB 147                 // 146*14 + 4 = 2048 rows
#define TPB 512
#define NWARP 16
#define JW (TAGS / NWARP)      // 128 j-columns per warp
#define JL (JW / 2)            // 64 j per lane
#define EH2 (JL / 2)           // 32 half2 E registers per lane
#define PSTRIDE 20             // partial row stride (floats): 16B-aligned, low-conflict
#define ALPHA 8.0f
#define START_IDX 0
#define END_IDX 1

// Persistent device state (no allocations allowed).
__device__ float g_Mbuf[S_LEN + 2];   // Mbuf[t] = max of r_t (Mbuf[0] = 1); nonneg => u32 red.max OK
__device__ float g_wbuf[2][TAGS];     // double-buffered carried vector
__device__ unsigned g_arrive;         // monotonic arrive counter

__global__ void crf_init() {
    int i = blockIdx.x * blockDim.x + threadIdx.x;
    int n = gridDim.x * blockDim.x;
    for (int t = i; t < S_LEN + 2; t += n) g_Mbuf[t] = (t == 0) ? 1.0f : 0.0f;
    for (int j = i; j < TAGS; j += n) {
        g_wbuf[0][j] = (j == START_IDX) ? 1.0f : 0.0f;
        g_wbuf[1][j] = 0.0f;
    }
    if (i == 0) g_arrive = 0u;
}

__device__ __forceinline__ __half2 f_as_h2(const float& f) {
    return *reinterpret_cast<const __half2*>(&f);
}
__device__ __forceinline__ float4 add4(float4 a, float4 b) {
    return make_float4(a.x + b.x, a.y + b.y, a.z + b.z, a.w + b.w);
}

__global__ void __launch_bounds__(TPB, 1) crf_main(const float* __restrict__ h,
                                                   const float* __restrict__ tr,
                                                   float* __restrict__ out) {
    __shared__ __half2 vbuf[TAGS / 2];          // 4KB: current v as half2 (warp-private slices)
    __shared__ float P[2 * RPB][PSTRIDE];       // transposed partials: P[laneSlot][warp]
    __shared__ double redd[TPB];                // epilogue scratch

    const int tid = threadIdx.x;
    const int warp = tid >> 5, lane = tid & 31;
    const int b = blockIdx.x;
    const int row0 = b * RPB;
    int nrows = TAGS - row0; if (nrows > RPB) nrows = RPB;

    const bool act = lane < 2 * RPB;
    const int row = (lane < RPB) ? lane : lane - RPB;
    const int jh = (lane >= RPB) ? 1 : 0;

    // ---- One-time: this lane's E chunk = exp(transitions) -> 32 half2 registers ----
    __half2 E2[EH2];
    if (act && row < nrows) {
        const float* trow = tr + (size_t)(row0 + row) * TAGS + warp * JW + jh * JL;
#pragma unroll
        for (int q = 0; q < EH2; q++)
            E2[q] = __floats2half2_rn(__expf(trow[2 * q]), __expf(trow[2 * q + 1]));
    } else {
#pragma unroll
        for (int q = 0; q < EH2; q++) E2[q] = __floats2half2_rn(0.f, 0.f);
    }

    const float4* v4base = reinterpret_cast<const float4*>(vbuf) + (warp * 16 + jh * 8);
    const bool comb = (warp == 0) && (lane < nrows);

    // h pipeline: hv holds emissions for the step about to run (loaded one step ahead).
    float hv = comb ? __ldcg(h + row0 + lane) : 0.f;

    for (int t = 0; t < S_LEN; t++) {
        // ---- wait for step-t inputs (one poller, block release) ----
        if (t > 0) {
            if (tid == 0) {
                unsigned target = (unsigned)t * NB, c;
                do {
                    asm volatile("ld.relaxed.gpu.global.u32 %0, [%1];"
                                 : "=r"(c) : "l"(&g_arrive));
                } while (c < target);
                asm volatile("fence.acq_rel.gpu;" ::: "memory");
            }
            __syncthreads();
        }

        // ---- off-critical-path: exp of current emissions, prefetch next step's ----
        float ehv = __expf(hv);
        if (comb && t + 1 < S_LEN)
            hv = __ldcg(h + (size_t)(t + 1) * TAGS + row0 + lane);

        // ---- v prep: scale + fp16 convert into warp-private smem slice ----
        {
            float m = __ldcg(&g_Mbuf[t]);
            float s = __fdividef(ALPHA, m);
            float4 x = __ldcg(reinterpret_cast<const float4*>(g_wbuf[t & 1]) + tid);
            vbuf[2 * tid]     = __floats2half2_rn(x.x * s, x.y * s);
            vbuf[2 * tid + 1] = __floats2half2_rn(x.z * s, x.w * s);
        }
        __syncwarp();   // vbuf slice is produced and consumed by this warp only

        // ---- 64-j dot fragment per lane: 4 chains of 8 half2 (16 fp16 terms) ----
        float f0 = 0.f, f1 = 0.f;
#pragma unroll
        for (int c = 0; c < 4; c++) {
            float4 va = v4base[2 * c];
            float4 vb = v4base[2 * c + 1];
            __half2 acc = __hmul2(E2[8 * c + 0], f_as_h2(va.x));
            acc = __hfma2(E2[8 * c + 1], f_as_h2(va.y), acc);
            acc = __hfma2(E2[8 * c + 2], f_as_h2(va.z), acc);
            acc = __hfma2(E2[8 * c + 3], f_as_h2(va.w), acc);
            acc = __hfma2(E2[8 * c + 4], f_as_h2(vb.x), acc);
            acc = __hfma2(E2[8 * c + 5], f_as_h2(vb.y), acc);
            acc = __hfma2(E2[8 * c + 6], f_as_h2(vb.z), acc);
            acc = __hfma2(E2[8 * c + 7], f_as_h2(vb.w), acc);
            float2 ff = __half22float2(acc);
            f0 += ff.x; f1 += ff.y;
        }
        if (act) P[lane][warp] = f0 + f1;
        __syncthreads();

        // ---- combine (warp 0), publish w, single REDUX max, single arrive ----
        if (warp == 0) {
            float wv = 0.f;
            if (comb) {
                const float4* Pr = reinterpret_cast<const float4*>(P[lane]);
                const float4* Qr = reinterpret_cast<const float4*>(P[lane + RPB]);
                float4 s4 = add4(add4(add4(Pr[0], Pr[1]), add4(Pr[2], Pr[3])),
                                 add4(add4(Qr[0], Qr[1]), add4(Qr[2], Qr[3])));
                float sum = (s4.x + s4.y) + (s4.z + s4.w);
                wv = ehv * sum;
                __stcg(&g_wbuf[(t + 1) & 1][row0 + lane], wv);
            }
            // wv >= 0 so uint order == float order; inactive lanes contribute 0.
            unsigned u = __reduce_max_sync(0xffffffffu, __float_as_uint(wv));
            if (lane == 0) {
                asm volatile("red.relaxed.gpu.global.max.u32 [%0], %1;"
                             :: "l"(reinterpret_cast<unsigned*>(&g_Mbuf[t + 1])),
                                "r"(u) : "memory");
                asm volatile("fence.acq_rel.gpu;" ::: "memory");
                asm volatile("red.relaxed.gpu.global.add.u32 [%0], %1;"
                             :: "l"(&g_arrive), "r"(1u) : "memory");
            }
        }
        // (top-of-loop syncthreads gates reuse of vbuf/P)
    }

    // ---- epilogue: block 0 only ----
    if (b == 0) {
        if (tid == 0) {
            unsigned target = (unsigned)NB * (unsigned)S_LEN, c;
            do {
                asm volatile("ld.relaxed.gpu.global.u32 %0, [%1];" : "=r"(c) : "l"(&g_arrive));
            } while (c < target);
            asm volatile("fence.acq_rel.gpu;" ::: "memory");
        }
        __syncthreads();

        float* redf = reinterpret_cast<float*>(vbuf);   // 512 floats <= 4KB
        const float* rS = g_wbuf[S_LEN & 1];
        float dpart = 0.f;
        for (int j = tid; j < TAGS; j += TPB)
            dpart += __ldcg(&rS[j]) * __expf(tr[(size_t)END_IDX * TAGS + j]);
        double lpart = 0.0;
        for (int t = tid; t < S_LEN; t += TPB)
            lpart += log((double)__ldcg(&g_Mbuf[t]));
        redf[tid] = dpart;
        redd[tid] = lpart;
        __syncthreads();
        for (int off = TPB / 2; off > 0; off >>= 1) {
            if (tid < off) { redf[tid] += redf[tid + off]; redd[tid] += redd[tid + off]; }
            __syncthreads();
        }
        if (tid == 0)
            out[0] = (float)(redd[0] + log((double)redf[0]) -
                             (double)S_LEN * log((double)ALPHA));
    }
}

extern "C" void kernel_launch(void* const* d_in, const int* in_sizes, int n_in,
                              void* d_out, int out_size) {
    const float* a = (const float*)d_in[0];
    const float* bb = (const float*)d_in[1];
    const float* h;
    const float* tr;
    if (in_sizes[0] == S_LEN * TAGS) { h = a; tr = bb; }
    else { h = bb; tr = a; }

    crf_init<<<64, 256>>>();
    crf_main<<<NB, TPB>>>(h, tr, (float*)d_out);
}